// round 7
// baseline (speedup 1.0000x reference)
#include <cuda_runtime.h>
#include <cstdint>
#include <math.h>

#define D    128
#define S_MAX 125000
#define EPS  1e-13f

// Scratch (static device globals -- no allocation)
__device__ unsigned int g_y[(size_t)S_MAX * D];  // 64 MB: y in tf32 bit pattern
__device__ float g_sg[S_MAX];                    // per-segment gate sum
__device__ int   g_starts[S_MAX + 1];            // segment start offsets

// ---------------------------------------------------------------------------
// Kernel 1: segment start offsets from the sorted index array (int4 scan).
// ---------------------------------------------------------------------------
__global__ void seg_starts_kernel(const int* __restrict__ idx, int N, int S) {
    int t  = blockIdx.x * blockDim.x + threadIdx.x;
    int n0 = t * 4;
    if (n0 >= N) return;

    int v0, v1, v2, v3;
    if (n0 + 3 < N) {
        int4 c = *(const int4*)(idx + n0);
        v0 = c.x; v1 = c.y; v2 = c.z; v3 = c.w;
    } else {
        v0 = idx[n0];
        v1 = (n0 + 1 < N) ? idx[n0 + 1] : v0;
        v2 = (n0 + 2 < N) ? idx[n0 + 2] : v1;
        v3 = (n0 + 3 < N) ? idx[n0 + 3] : v2;
    }
    int prev = (n0 == 0) ? -1 : idx[n0 - 1];

    int vals[4] = {v0, v1, v2, v3};
    #pragma unroll
    for (int j = 0; j < 4; ++j) {
        if (n0 + j < N) {
            int cur = vals[j];
            for (int s = prev + 1; s <= cur; ++s) g_starts[s] = n0 + j;
            prev = cur;
        }
    }
    if (n0 + 4 >= N) {
        for (int s = prev + 1; s <= S; ++s) g_starts[s] = N;
    }
}

__device__ __forceinline__ float dot4(float4 a, float4 b) {
    return a.x * b.x + a.y * b.y + a.z * b.z + a.w * b.w;
}

__device__ __forceinline__ uint32_t f2tf32(float f) {
    uint32_t r;
    asm("cvt.rna.tf32.f32 %0, %1;" : "=r"(r) : "f"(f));
    return r;
}

// ---------------------------------------------------------------------------
// Kernel 2: single-pass fused gate + weighted segment aggregation.
//   y_s = (Sum_r g_r x_r) / denom,  g_r = w_r exp(x_r.Wg + bg)
// One warp per segment; lane l owns columns [4l,4l+4) throughout.
// 8 rows per batch (two XOR quads) -> 9 LDGs in flight per iteration.
// Quadrant q owns rows base+q and base+4+q; loads use XOR-permuted order
// v_m = x[base+(q^m)], u_m = x[base+4+(q^m)] so the two 4-row dot
// reductions cost 6 shuffles each and gate broadcast is statically paired.
// Epilogue stores y as tf32 bit pattern (feeds tf32 MMA unchanged).
// ---------------------------------------------------------------------------
__global__ void __launch_bounds__(256)
agg_kernel(const float* __restrict__ x,
           const float* __restrict__ w,
           const float* __restrict__ Wg,
           const float* __restrict__ bgp,
           int S) {
    int warp = (int)((blockIdx.x * (unsigned)blockDim.x + threadIdx.x) >> 5);
    if (warp >= S) return;
    int lane = threadIdx.x & 31;
    int q    = lane >> 3;

    int r0  = g_starts[warp];
    int len = g_starts[warp + 1] - r0;

    float4 wg  = *(const float4*)(Wg + lane * 4);
    float  bg0 = bgp[0];
    const float* xb = x + (size_t)r0 * D + lane * 4;

    int pm1 = q ^ 1, pm2 = q ^ 2, pm3 = q ^ 3;

    float4 acc = make_float4(0.f, 0.f, 0.f, 0.f);
    float  denom = 0.f;

    for (int base = 0; base < len; base += 8) {
        int rA = base + q,   rB = base + pm1, rC = base + pm2, rD = base + pm3;
        int sA = rA + 4,     sB = rB + 4,     sC = rC + 4,     sD = rD + 4;

        float4 z = make_float4(0.f,0.f,0.f,0.f);
        float4 v0 = z, v1 = z, v2 = z, v3 = z;
        float4 u0 = z, u1 = z, u2 = z, u3 = z;
        if (rA < len) v0 = *(const float4*)(xb + (size_t)rA * D);
        if (rB < len) v1 = *(const float4*)(xb + (size_t)rB * D);
        if (rC < len) v2 = *(const float4*)(xb + (size_t)rC * D);
        if (rD < len) v3 = *(const float4*)(xb + (size_t)rD * D);
        if (sA < len) u0 = *(const float4*)(xb + (size_t)sA * D);
        if (sB < len) u1 = *(const float4*)(xb + (size_t)sB * D);
        if (sC < len) u2 = *(const float4*)(xb + (size_t)sC * D);
        if (sD < len) u3 = *(const float4*)(xb + (size_t)sD * D);
        float wrV = (rA < len) ? w[r0 + rA] : 0.f;
        float wrU = (sA < len) ? w[r0 + sA] : 0.f;

        // two independent 4-row reductions (interleave for ILP)
        float pV0 = dot4(v0, wg), pV1 = dot4(v1, wg);
        float pV2 = dot4(v2, wg), pV3 = dot4(v3, wg);
        float pU0 = dot4(u0, wg), pU1 = dot4(u1, wg);
        float pU2 = dot4(u2, wg), pU3 = dot4(u3, wg);

        float tV01 = pV0 + __shfl_xor_sync(0xffffffffu, pV1, 8);
        float tU01 = pU0 + __shfl_xor_sync(0xffffffffu, pU1, 8);
        float tV23 = pV2 + __shfl_xor_sync(0xffffffffu, pV3, 8);
        float tU23 = pU2 + __shfl_xor_sync(0xffffffffu, pU3, 8);
        float tV = tV01 + __shfl_xor_sync(0xffffffffu, tV23, 16);
        float tU = tU01 + __shfl_xor_sync(0xffffffffu, tU23, 16);
        tV += __shfl_xor_sync(0xffffffffu, tV, 1);
        tU += __shfl_xor_sync(0xffffffffu, tU, 1);
        tV += __shfl_xor_sync(0xffffffffu, tV, 2);
        tU += __shfl_xor_sync(0xffffffffu, tU, 2);
        tV += __shfl_xor_sync(0xffffffffu, tV, 4);
        tU += __shfl_xor_sync(0xffffffffu, tU, 4);

        float g = wrV * __expf(tV + bg0);
        float h = wrU * __expf(tU + bg0);
        denom += g + h;

        float g1 = __shfl_xor_sync(0xffffffffu, g, 8);
        float h1 = __shfl_xor_sync(0xffffffffu, h, 8);
        float g2 = __shfl_xor_sync(0xffffffffu, g, 16);
        float h2 = __shfl_xor_sync(0xffffffffu, h, 16);
        float g3 = __shfl_xor_sync(0xffffffffu, g, 24);
        float h3 = __shfl_xor_sync(0xffffffffu, h, 24);

        acc.x += g * v0.x + g1 * v1.x + g2 * v2.x + g3 * v3.x
               + h * u0.x + h1 * u1.x + h2 * u2.x + h3 * u3.x;
        acc.y += g * v0.y + g1 * v1.y + g2 * v2.y + g3 * v3.y
               + h * u0.y + h1 * u1.y + h2 * u2.y + h3 * u3.y;
        acc.z += g * v0.z + g1 * v1.z + g2 * v2.z + g3 * v3.z
               + h * u0.z + h1 * u1.z + h2 * u2.z + h3 * u3.z;
        acc.w += g * v0.w + g1 * v1.w + g2 * v2.w + g3 * v3.w
               + h * u0.w + h1 * u1.w + h2 * u2.w + h3 * u3.w;
    }

    denom += __shfl_xor_sync(0xffffffffu, denom, 8);
    denom += __shfl_xor_sync(0xffffffffu, denom, 16);

    float inv = 1.f / (denom + EPS);
    uint4 o;
    o.x = f2tf32(acc.x * inv); o.y = f2tf32(acc.y * inv);
    o.z = f2tf32(acc.z * inv); o.w = f2tf32(acc.w * inv);
    *(uint4*)(g_y + (size_t)warp * D + lane * 4) = o;
    if (lane == 0) g_sg[warp] = denom * inv;
}

// ---------------------------------------------------------------------------
// Kernel 3: out[S,128] = y @ Wm + sg (x) bm    (tf32 mma.sync, fp32 accum)
// y already in tf32 bits; Wm converted to tf32 during staging; wS padded to
// stride 136 (mod32 = 8 -> bank = 8tg+grp, conflict-free b-frag loads).
// Mainloop is pure LDS + MMA.
// ---------------------------------------------------------------------------
#define BM 128
#define BN 128
#define BK 32
#define WPAD 8   // wS stride = BN+WPAD = 136: 16B-aligned rows, conflict-free

__device__ __forceinline__ void mma_tf32(float* c, const uint32_t* a, const uint32_t* b) {
    asm volatile(
        "mma.sync.aligned.m16n8k8.row.col.f32.tf32.tf32.f32 "
        "{%0,%1,%2,%3}, {%4,%5,%6,%7}, {%8,%9}, {%0,%1,%2,%3};\n"
        : "+f"(c[0]), "+f"(c[1]), "+f"(c[2]), "+f"(c[3])
        : "r"(a[0]), "r"(a[1]), "r"(a[2]), "r"(a[3]), "r"(b[0]), "r"(b[1]));
}

__global__ void __launch_bounds__(256)
gemm_kernel(const float* __restrict__ Wm,
            const float* __restrict__ bm,
            float* __restrict__ out, int S) {
    __shared__ uint32_t yS[BM][BK + 4];        // stride 36: a-frags conflict-free
    __shared__ uint32_t wS[BK][BN + WPAD];     // stride 136: b-frags conflict-free

    int tid  = threadIdx.x;
    int wid  = tid >> 5;
    int lane = tid & 31;
    int warp_m = wid & 3;
    int warp_n = wid >> 2;
    int grp = lane >> 2;
    int tg  = lane & 3;
    int rowbase = blockIdx.x * BM;

    float c[2][8][4];
    #pragma unroll
    for (int mf = 0; mf < 2; ++mf)
        #pragma unroll
        for (int nf = 0; nf < 8; ++nf)
            #pragma unroll
            for (int i = 0; i < 4; ++i) c[mf][nf][i] = 0.f;

    for (int kt = 0; kt < D; kt += BK) {
        __syncthreads();
        {
            int r  = tid >> 3;
            int qq = tid & 7;
            #pragma unroll
            for (int it = 0; it < 4; ++it) {
                int row  = r + it * 32;
                int grow = rowbase + row;
                uint4 v = make_uint4(0u, 0u, 0u, 0u);
                if (grow < S)
                    v = *(const uint4*)(g_y + (size_t)grow * D + kt + qq * 4);
                *(uint4*)&yS[row][qq * 4] = v;
            }
            int k = tid >> 3;
            #pragma unroll
            for (int it = 0; it < 4; ++it) {
                int q2 = (tid & 7) + it * 8;
                float4 t = *(const float4*)(Wm + (size_t)(kt + k) * D + q2 * 4);
                uint4 u;
                u.x = f2tf32(t.x); u.y = f2tf32(t.y);
                u.z = f2tf32(t.z); u.w = f2tf32(t.w);
                *(uint4*)&wS[k][q2 * 4] = u;
            }
        }
        __syncthreads();

        #pragma unroll
        for (int ks = 0; ks < BK; ks += 8) {
            uint32_t a[2][4];
            uint32_t b[8][2];
            #pragma unroll
            for (int mf = 0; mf < 2; ++mf) {
                int r = warp_m * 32 + mf * 16;
                a[mf][0] = yS[r + grp    ][ks + tg    ];
                a[mf][1] = yS[r + grp + 8][ks + tg    ];
                a[mf][2] = yS[r + grp    ][ks + tg + 4];
                a[mf][3] = yS[r + grp + 8][ks + tg + 4];
            }
            #pragma unroll
            for (int nf = 0; nf < 8; ++nf) {
                int col = warp_n * 64 + nf * 8 + grp;
                b[nf][0] = wS[ks + tg    ][col];
                b[nf][1] = wS[ks + tg + 4][col];
            }
            #pragma unroll
            for (int mf = 0; mf < 2; ++mf)
                #pragma unroll
                for (int nf = 0; nf < 8; ++nf)
                    mma_tf32(c[mf][nf], a[mf], b[nf]);
        }
    }

    #pragma unroll
    for (int mf = 0; mf < 2; ++mf) {
        int row0 = rowbase + warp_m * 32 + mf * 16 + grp;
        int row1 = row0 + 8;
        float sgA = (row0 < S) ? g_sg[row0] : 0.f;
        float sgB = (row1 < S) ? g_sg[row1] : 0.f;
        #pragma unroll
        for (int nf = 0; nf < 8; ++nf) {
            int col = warp_n * 64 + nf * 8 + tg * 2;
            float b0 = bm[col], b1 = bm[col + 1];
            if (row0 < S) {
                float2 o;
                o.x = c[mf][nf][0] + sgA * b0;
                o.y = c[mf][nf][1] + sgA * b1;
                *(float2*)(out + (size_t)row0 * D + col) = o;
            }
            if (row1 < S) {
                float2 o;
                o.x = c[mf][nf][2] + sgB * b0;
                o.y = c[mf][nf][3] + sgB * b1;
                *(float2*)(out + (size_t)row1 * D + col) = o;
            }
        }
    }
}

// ---------------------------------------------------------------------------
extern "C" void kernel_launch(void* const* d_in, const int* in_sizes, int n_in,
                              void* d_out, int out_size) {
    const float* x   = (const float*)d_in[0];
    const int*   idx = (const int*)  d_in[1];
    const float* w   = (const float*)d_in[2];
    const float* Wg  = (const float*)d_in[3];
    const float* bg  = (const float*)d_in[4];
    const float* Wm  = (const float*)d_in[5];
    const float* bm  = (const float*)d_in[6];
    float* out = (float*)d_out;

    int N = in_sizes[1];
    int S = out_size / D;

    int quads = (N + 3) / 4;
    seg_starts_kernel<<<(quads + 255) / 256, 256>>>(idx, N, S);

    long long total_threads = (long long)S * 32;
    int agg_blocks = (int)((total_threads + 255) / 256);
    agg_kernel<<<agg_blocks, 256>>>(x, w, Wg, bg, S);

    gemm_kernel<<<(S + BM - 1) / BM, 256>>>(Wm, bm, out, S);
}

// round 8
// speedup vs baseline: 1.0351x; 1.0351x over previous
#include <cuda_runtime.h>
#include <cstdint>
#include <math.h>

#define D    128
#define S_MAX 125000
#define EPS  1e-13f

// Scratch (static device globals -- no allocation)
__device__ unsigned int g_y[(size_t)S_MAX * D];  // 64 MB: y in tf32 bit pattern
__device__ float g_sg[S_MAX];                    // per-segment gate sum
__device__ int   g_starts[S_MAX + 1];            // segment start offsets

// ---------------------------------------------------------------------------
// Kernel 1: segment start offsets from the sorted index array (int4 scan).
// ---------------------------------------------------------------------------
__global__ void seg_starts_kernel(const int* __restrict__ idx, int N, int S) {
    int t  = blockIdx.x * blockDim.x + threadIdx.x;
    int n0 = t * 4;
    if (n0 >= N) return;

    int v0, v1, v2, v3;
    if (n0 + 3 < N) {
        int4 c = *(const int4*)(idx + n0);
        v0 = c.x; v1 = c.y; v2 = c.z; v3 = c.w;
    } else {
        v0 = idx[n0];
        v1 = (n0 + 1 < N) ? idx[n0 + 1] : v0;
        v2 = (n0 + 2 < N) ? idx[n0 + 2] : v1;
        v3 = (n0 + 3 < N) ? idx[n0 + 3] : v2;
    }
    int prev = (n0 == 0) ? -1 : idx[n0 - 1];

    int vals[4] = {v0, v1, v2, v3};
    #pragma unroll
    for (int j = 0; j < 4; ++j) {
        if (n0 + j < N) {
            int cur = vals[j];
            for (int s = prev + 1; s <= cur; ++s) g_starts[s] = n0 + j;
            prev = cur;
        }
    }
    if (n0 + 4 >= N) {
        for (int s = prev + 1; s <= S; ++s) g_starts[s] = N;
    }
}

__device__ __forceinline__ float dot4(float4 a, float4 b) {
    return a.x * b.x + a.y * b.y + a.z * b.z + a.w * b.w;
}

__device__ __forceinline__ uint32_t f2tf32(float f) {
    uint32_t r;
    asm("cvt.rna.tf32.f32 %0, %1;" : "=r"(r) : "f"(f));
    return r;
}

// ---------------------------------------------------------------------------
// Kernel 2: single-pass fused gate + weighted segment aggregation.
// EXACT R6 structure (best known): 4-row XOR batches, low register pressure.
// Only change: epilogue stores y as tf32 bit pattern (feeds gemm directly).
// ---------------------------------------------------------------------------
__global__ void __launch_bounds__(256)
agg_kernel(const float* __restrict__ x,
           const float* __restrict__ w,
           const float* __restrict__ Wg,
           const float* __restrict__ bgp,
           int S) {
    int warp = (int)((blockIdx.x * (unsigned)blockDim.x + threadIdx.x) >> 5);
    if (warp >= S) return;
    int lane = threadIdx.x & 31;
    int q    = lane >> 3;                 // quadrant: owns row base+q

    int r0  = g_starts[warp];
    int len = g_starts[warp + 1] - r0;

    float4 wg  = *(const float4*)(Wg + lane * 4);
    float  bg0 = bgp[0];
    const float* xb = x + (size_t)r0 * D + lane * 4;

    int pm1 = q ^ 1, pm2 = q ^ 2, pm3 = q ^ 3;   // permuted row slots

    float4 acc = make_float4(0.f, 0.f, 0.f, 0.f);
    float  denom = 0.f;                   // per-quadrant partial

    for (int base = 0; base < len; base += 4) {
        int rA = base + q;                // own row
        int rB = base + pm1;
        int rC = base + pm2;
        int rD = base + pm3;

        float4 v0 = make_float4(0.f,0.f,0.f,0.f), v1 = v0, v2 = v0, v3 = v0;
        if (rA < len) v0 = *(const float4*)(xb + (size_t)rA * D);
        if (rB < len) v1 = *(const float4*)(xb + (size_t)rB * D);
        if (rC < len) v2 = *(const float4*)(xb + (size_t)rC * D);
        if (rD < len) v3 = *(const float4*)(xb + (size_t)rD * D);
        float wr = (rA < len) ? w[r0 + rA] : 0.f;

        // partial dots: p_m = <v_m, wg> = partial of row base+(q^m) at cols 4l
        float p0 = dot4(v0, wg);
        float p1 = dot4(v1, wg);
        float p2 = dot4(v2, wg);
        float p3 = dot4(v3, wg);

        // redistribute + reduce: quadrant q ends with row base+q's full dot
        float t01 = p0 + __shfl_xor_sync(0xffffffffu, p1, 8);
        float t23 = p2 + __shfl_xor_sync(0xffffffffu, p3, 8);
        float t   = t01 + __shfl_xor_sync(0xffffffffu, t23, 16);
        t += __shfl_xor_sync(0xffffffffu, t, 1);
        t += __shfl_xor_sync(0xffffffffu, t, 2);
        t += __shfl_xor_sync(0xffffffffu, t, 4);

        float g = wr * __expf(t + bg0);   // gate of own row (0 if invalid)
        denom += g;

        // static broadcast: g_m = gate of row base+(q^m), pairs with v_m
        float g1 = __shfl_xor_sync(0xffffffffu, g, 8);
        float g2 = __shfl_xor_sync(0xffffffffu, g, 16);
        float g3 = __shfl_xor_sync(0xffffffffu, g, 24);

        acc.x += g * v0.x + g1 * v1.x + g2 * v2.x + g3 * v3.x;
        acc.y += g * v0.y + g1 * v1.y + g2 * v2.y + g3 * v3.y;
        acc.z += g * v0.z + g1 * v1.z + g2 * v2.z + g3 * v3.z;
        acc.w += g * v0.w + g1 * v1.w + g2 * v2.w + g3 * v3.w;
    }

    // combine per-quadrant denoms (lanes within a quadrant agree)
    denom += __shfl_xor_sync(0xffffffffu, denom, 8);
    denom += __shfl_xor_sync(0xffffffffu, denom, 16);

    float inv = 1.f / (denom + EPS);
    uint4 o;
    o.x = f2tf32(acc.x * inv); o.y = f2tf32(acc.y * inv);
    o.z = f2tf32(acc.z * inv); o.w = f2tf32(acc.w * inv);
    *(uint4*)(g_y + (size_t)warp * D + lane * 4) = o;
    if (lane == 0) g_sg[warp] = denom * inv;
}

// ---------------------------------------------------------------------------
// Kernel 3: out[S,128] = y @ Wm + sg (x) bm    (tf32 mma.sync, fp32 accum)
// y already in tf32 bits; Wm converted to tf32 during staging; wS padded to
// stride 136 (mod32 = 8 -> bank = 8tg+grp, conflict-free b-frag loads).
// Mainloop is pure LDS + MMA.
// ---------------------------------------------------------------------------
#define BM 128
#define BN 128
#define BK 32
#define WPAD 8   // wS stride = BN+WPAD = 136: 16B-aligned rows, conflict-free

__device__ __forceinline__ void mma_tf32(float* c, const uint32_t* a, const uint32_t* b) {
    asm volatile(
        "mma.sync.aligned.m16n8k8.row.col.f32.tf32.tf32.f32 "
        "{%0,%1,%2,%3}, {%4,%5,%6,%7}, {%8,%9}, {%0,%1,%2,%3};\n"
        : "+f"(c[0]), "+f"(c[1]), "+f"(c[2]), "+f"(c[3])
        : "r"(a[0]), "r"(a[1]), "r"(a[2]), "r"(a[3]), "r"(b[0]), "r"(b[1]));
}

__global__ void __launch_bounds__(256)
gemm_kernel(const float* __restrict__ Wm,
            const float* __restrict__ bm,
            float* __restrict__ out, int S) {
    __shared__ uint32_t yS[BM][BK + 4];        // stride 36: a-frags conflict-free
    __shared__ uint32_t wS[BK][BN + WPAD];     // stride 136: b-frags conflict-free

    int tid  = threadIdx.x;
    int wid  = tid >> 5;
    int lane = tid & 31;
    int warp_m = wid & 3;
    int warp_n = wid >> 2;
    int grp = lane >> 2;
    int tg  = lane & 3;
    int rowbase = blockIdx.x * BM;

    float c[2][8][4];
    #pragma unroll
    for (int mf = 0; mf < 2; ++mf)
        #pragma unroll
        for (int nf = 0; nf < 8; ++nf)
            #pragma unroll
            for (int i = 0; i < 4; ++i) c[mf][nf][i] = 0.f;

    for (int kt = 0; kt < D; kt += BK) {
        __syncthreads();
        {
            int r  = tid >> 3;
            int qq = tid & 7;
            #pragma unroll
            for (int it = 0; it < 4; ++it) {
                int row  = r + it * 32;
                int grow = rowbase + row;
                uint4 v = make_uint4(0u, 0u, 0u, 0u);
                if (grow < S)
                    v = *(const uint4*)(g_y + (size_t)grow * D + kt + qq * 4);
                *(uint4*)&yS[row][qq * 4] = v;
            }
            int k = tid >> 3;
            #pragma unroll
            for (int it = 0; it < 4; ++it) {
                int q2 = (tid & 7) + it * 8;
                float4 t = *(const float4*)(Wm + (size_t)(kt + k) * D + q2 * 4);
                uint4 u;
                u.x = f2tf32(t.x); u.y = f2tf32(t.y);
                u.z = f2tf32(t.z); u.w = f2tf32(t.w);
                *(uint4*)&wS[k][q2 * 4] = u;
            }
        }
        __syncthreads();

        #pragma unroll
        for (int ks = 0; ks < BK; ks += 8) {
            uint32_t a[2][4];
            uint32_t b[8][2];
            #pragma unroll
            for (int mf = 0; mf < 2; ++mf) {
                int r = warp_m * 32 + mf * 16;
                a[mf][0] = yS[r + grp    ][ks + tg    ];
                a[mf][1] = yS[r + grp + 8][ks + tg    ];
                a[mf][2] = yS[r + grp    ][ks + tg + 4];
                a[mf][3] = yS[r + grp + 8][ks + tg + 4];
            }
            #pragma unroll
            for (int nf = 0; nf < 8; ++nf) {
                int col = warp_n * 64 + nf * 8 + grp;
                b[nf][0] = wS[ks + tg    ][col];
                b[nf][1] = wS[ks + tg + 4][col];
            }
            #pragma unroll
            for (int mf = 0; mf < 2; ++mf)
                #pragma unroll
                for (int nf = 0; nf < 8; ++nf)
                    mma_tf32(c[mf][nf], a[mf], b[nf]);
        }
    }

    #pragma unroll
    for (int mf = 0; mf < 2; ++mf) {
        int row0 = rowbase + warp_m * 32 + mf * 16 + grp;
        int row1 = row0 + 8;
        float sgA = (row0 < S) ? g_sg[row0] : 0.f;
        float sgB = (row1 < S) ? g_sg[row1] : 0.f;
        #pragma unroll
        for (int nf = 0; nf < 8; ++nf) {
            int col = warp_n * 64 + nf * 8 + tg * 2;
            float b0 = bm[col], b1 = bm[col + 1];
            if (row0 < S) {
                float2 o;
                o.x = c[mf][nf][0] + sgA * b0;
                o.y = c[mf][nf][1] + sgA * b1;
                *(float2*)(out + (size_t)row0 * D + col) = o;
            }
            if (row1 < S) {
                float2 o;
                o.x = c[mf][nf][2] + sgB * b0;
                o.y = c[mf][nf][3] + sgB * b1;
                *(float2*)(out + (size_t)row1 * D + col) = o;
            }
        }
    }
}

// ---------------------------------------------------------------------------
extern "C" void kernel_launch(void* const* d_in, const int* in_sizes, int n_in,
                              void* d_out, int out_size) {
    const float* x   = (const float*)d_in[0];
    const int*   idx = (const int*)  d_in[1];
    const float* w   = (const float*)d_in[2];
    const float* Wg  = (const float*)d_in[3];
    const float* bg  = (const float*)d_in[4];
    const float* Wm  = (const float*)d_in[5];
    const float* bm  = (const float*)d_in[6];
    float* out = (float*)d_out;

    int N = in_sizes[1];
    int S = out_size / D;

    int quads = (N + 3) / 4;
    seg_starts_kernel<<<(quads + 255) / 256, 256>>>(idx, N, S);

    long long total_threads = (long long)S * 32;
    int agg_blocks = (int)((total_threads + 255) / 256);
    agg_kernel<<<agg_blocks, 256>>>(x, w, Wg, bg, S);

    gemm_kernel<<<(S + BM - 1) / BM, 256>>>(Wm, bm, out, S);
}

// round 9
// speedup vs baseline: 1.0862x; 1.0494x over previous
#include <cuda_runtime.h>
#include <cstdint>
#include <math.h>

#define D    128
#define S_MAX 125000
#define EPS  1e-13f

// Scratch (static device globals -- no allocation)
__device__ unsigned int g_y[(size_t)S_MAX * D];  // 64 MB: y in tf32 bit pattern
__device__ float g_sg[S_MAX];                    // per-segment gate sum
__device__ int   g_starts[S_MAX + 1];            // segment start offsets

// ---------------------------------------------------------------------------
// Kernel 1: segment start offsets from the sorted index array (int4 scan).
// ---------------------------------------------------------------------------
__global__ void seg_starts_kernel(const int* __restrict__ idx, int N, int S) {
    int t  = blockIdx.x * blockDim.x + threadIdx.x;
    int n0 = t * 4;
    if (n0 >= N) return;

    int v0, v1, v2, v3;
    if (n0 + 3 < N) {
        int4 c = *(const int4*)(idx + n0);
        v0 = c.x; v1 = c.y; v2 = c.z; v3 = c.w;
    } else {
        v0 = idx[n0];
        v1 = (n0 + 1 < N) ? idx[n0 + 1] : v0;
        v2 = (n0 + 2 < N) ? idx[n0 + 2] : v1;
        v3 = (n0 + 3 < N) ? idx[n0 + 3] : v2;
    }
    int prev = (n0 == 0) ? -1 : idx[n0 - 1];

    int vals[4] = {v0, v1, v2, v3};
    #pragma unroll
    for (int j = 0; j < 4; ++j) {
        if (n0 + j < N) {
            int cur = vals[j];
            for (int s = prev + 1; s <= cur; ++s) g_starts[s] = n0 + j;
            prev = cur;
        }
    }
    if (n0 + 4 >= N) {
        for (int s = prev + 1; s <= S; ++s) g_starts[s] = N;
    }
}

__device__ __forceinline__ float dot4(float4 a, float4 b) {
    return a.x * b.x + a.y * b.y + a.z * b.z + a.w * b.w;
}

__device__ __forceinline__ uint32_t f2tf32(float f) {
    uint32_t r;
    asm("cvt.rna.tf32.f32 %0, %1;" : "=r"(r) : "f"(f));
    return r;
}

// ---------------------------------------------------------------------------
// Kernel 2: single-pass fused gate + weighted segment aggregation.
// LOAD-BALANCED: fixed grid; each warp sweeps a CONTIGUOUS run of ~14
// segments (imbalance averages over the run; no block-level max-of-8 tail;
// each warp streams a contiguous ~56KB region of x).
// Inner loop = exact R6 structure (4-row XOR batches, lean registers).
// ---------------------------------------------------------------------------
#define AGG_BLOCKS 1184   // 148 SMs x 8 blocks
#define AGG_WARPS  (AGG_BLOCKS * 8)

__global__ void __launch_bounds__(256)
agg_kernel(const float* __restrict__ x,
           const float* __restrict__ w,
           const float* __restrict__ Wg,
           const float* __restrict__ bgp,
           int S) {
    int gw   = (int)((blockIdx.x * (unsigned)blockDim.x + threadIdx.x) >> 5);
    int lane = threadIdx.x & 31;
    int q    = lane >> 3;
    int pm1 = q ^ 1, pm2 = q ^ 2, pm3 = q ^ 3;

    int per = (S + AGG_WARPS - 1) / AGG_WARPS;
    int s0  = gw * per;
    int s1  = s0 + per; if (s1 > S) s1 = S;
    if (s0 >= s1) return;

    float4 wg  = *(const float4*)(Wg + lane * 4);
    float  bg0 = bgp[0];

    int r0 = g_starts[s0];
    for (int s = s0; s < s1; ++s) {
        int r1  = g_starts[s + 1];
        int len = r1 - r0;
        const float* xb = x + (size_t)r0 * D + lane * 4;

        float4 acc = make_float4(0.f, 0.f, 0.f, 0.f);
        float  denom = 0.f;

        for (int base = 0; base < len; base += 4) {
            int rA = base + q;
            int rB = base + pm1;
            int rC = base + pm2;
            int rD = base + pm3;

            float4 v0 = make_float4(0.f,0.f,0.f,0.f), v1 = v0, v2 = v0, v3 = v0;
            if (rA < len) v0 = *(const float4*)(xb + (size_t)rA * D);
            if (rB < len) v1 = *(const float4*)(xb + (size_t)rB * D);
            if (rC < len) v2 = *(const float4*)(xb + (size_t)rC * D);
            if (rD < len) v3 = *(const float4*)(xb + (size_t)rD * D);
            float wr = (rA < len) ? w[r0 + rA] : 0.f;

            float p0 = dot4(v0, wg);
            float p1 = dot4(v1, wg);
            float p2 = dot4(v2, wg);
            float p3 = dot4(v3, wg);

            float t01 = p0 + __shfl_xor_sync(0xffffffffu, p1, 8);
            float t23 = p2 + __shfl_xor_sync(0xffffffffu, p3, 8);
            float t   = t01 + __shfl_xor_sync(0xffffffffu, t23, 16);
            t += __shfl_xor_sync(0xffffffffu, t, 1);
            t += __shfl_xor_sync(0xffffffffu, t, 2);
            t += __shfl_xor_sync(0xffffffffu, t, 4);

            float g = wr * __expf(t + bg0);
            denom += g;

            float g1 = __shfl_xor_sync(0xffffffffu, g, 8);
            float g2 = __shfl_xor_sync(0xffffffffu, g, 16);
            float g3 = __shfl_xor_sync(0xffffffffu, g, 24);

            acc.x += g * v0.x + g1 * v1.x + g2 * v2.x + g3 * v3.x;
            acc.y += g * v0.y + g1 * v1.y + g2 * v2.y + g3 * v3.y;
            acc.z += g * v0.z + g1 * v1.z + g2 * v2.z + g3 * v3.z;
            acc.w += g * v0.w + g1 * v1.w + g2 * v2.w + g3 * v3.w;
        }

        denom += __shfl_xor_sync(0xffffffffu, denom, 8);
        denom += __shfl_xor_sync(0xffffffffu, denom, 16);

        float inv = 1.f / (denom + EPS);
        uint4 o;
        o.x = f2tf32(acc.x * inv); o.y = f2tf32(acc.y * inv);
        o.z = f2tf32(acc.z * inv); o.w = f2tf32(acc.w * inv);
        *(uint4*)(g_y + (size_t)s * D + lane * 4) = o;
        if (lane == 0) g_sg[s] = denom * inv;

        r0 = r1;
    }
}

// ---------------------------------------------------------------------------
// Kernel 3: out[S,128] = y @ Wm + sg (x) bm    (tf32 mma.sync, fp32 accum)
// ---------------------------------------------------------------------------
#define BM 128
#define BN 128
#define BK 32
#define WPAD 8   // wS stride = 136: bank = 8tg+grp, conflict-free b-frag loads

__device__ __forceinline__ void mma_tf32(float* c, const uint32_t* a, const uint32_t* b) {
    asm volatile(
        "mma.sync.aligned.m16n8k8.row.col.f32.tf32.tf32.f32 "
        "{%0,%1,%2,%3}, {%4,%5,%6,%7}, {%8,%9}, {%0,%1,%2,%3};\n"
        : "+f"(c[0]), "+f"(c[1]), "+f"(c[2]), "+f"(c[3])
        : "r"(a[0]), "r"(a[1]), "r"(a[2]), "r"(a[3]), "r"(b[0]), "r"(b[1]));
}

__global__ void __launch_bounds__(256)
gemm_kernel(const float* __restrict__ Wm,
            const float* __restrict__ bm,
            float* __restrict__ out, int S) {
    __shared__ uint32_t yS[BM][BK + 4];
    __shared__ uint32_t wS[BK][BN + WPAD];

    int tid  = threadIdx.x;
    int wid  = tid >> 5;
    int lane = tid & 31;
    int warp_m = wid & 3;
    int warp_n = wid >> 2;
    int grp = lane >> 2;
    int tg  = lane & 3;
    int rowbase = blockIdx.x * BM;

    float c[2][8][4];
    #pragma unroll
    for (int mf = 0; mf < 2; ++mf)
        #pragma unroll
        for (int nf = 0; nf < 8; ++nf)
            #pragma unroll
            for (int i = 0; i < 4; ++i) c[mf][nf][i] = 0.f;

    for (int kt = 0; kt < D; kt += BK) {
        __syncthreads();
        {
            int r  = tid >> 3;
            int qq = tid & 7;
            #pragma unroll
            for (int it = 0; it < 4; ++it) {
                int row  = r + it * 32;
                int grow = rowbase + row;
                uint4 v = make_uint4(0u, 0u, 0u, 0u);
                if (grow < S)
                    v = *(const uint4*)(g_y + (size_t)grow * D + kt + qq * 4);
                *(uint4*)&yS[row][qq * 4] = v;
            }
            int k = tid >> 3;
            #pragma unroll
            for (int it = 0; it < 4; ++it) {
                int q2 = (tid & 7) + it * 8;
                float4 t = *(const float4*)(Wm + (size_t)(kt + k) * D + q2 * 4);
                uint4 u;
                u.x = f2tf32(t.x); u.y = f2tf32(t.y);
                u.z = f2tf32(t.z); u.w = f2tf32(t.w);
                *(uint4*)&wS[k][q2 * 4] = u;
            }
        }
        __syncthreads();

        #pragma unroll
        for (int ks = 0; ks < BK; ks += 8) {
            uint32_t a[2][4];
            uint32_t b[8][2];
            #pragma unroll
            for (int mf = 0; mf < 2; ++mf) {
                int r = warp_m * 32 + mf * 16;
                a[mf][0] = yS[r + grp    ][ks + tg    ];
                a[mf][1] = yS[r + grp + 8][ks + tg    ];
                a[mf][2] = yS[r + grp    ][ks + tg + 4];
                a[mf][3] = yS[r + grp + 8][ks + tg + 4];
            }
            #pragma unroll
            for (int nf = 0; nf < 8; ++nf) {
                int col = warp_n * 64 + nf * 8 + grp;
                b[nf][0] = wS[ks + tg    ][col];
                b[nf][1] = wS[ks + tg + 4][col];
            }
            #pragma unroll
            for (int mf = 0; mf < 2; ++mf)
                #pragma unroll
                for (int nf = 0; nf < 8; ++nf)
                    mma_tf32(c[mf][nf], a[mf], b[nf]);
        }
    }

    #pragma unroll
    for (int mf = 0; mf < 2; ++mf) {
        int row0 = rowbase + warp_m * 32 + mf * 16 + grp;
        int row1 = row0 + 8;
        float sgA = (row0 < S) ? g_sg[row0] : 0.f;
        float sgB = (row1 < S) ? g_sg[row1] : 0.f;
        #pragma unroll
        for (int nf = 0; nf < 8; ++nf) {
            int col = warp_n * 64 + nf * 8 + tg * 2;
            float b0 = bm[col], b1 = bm[col + 1];
            if (row0 < S) {
                float2 o;
                o.x = c[mf][nf][0] + sgA * b0;
                o.y = c[mf][nf][1] + sgA * b1;
                *(float2*)(out + (size_t)row0 * D + col) = o;
            }
            if (row1 < S) {
                float2 o;
                o.x = c[mf][nf][2] + sgB * b0;
                o.y = c[mf][nf][3] + sgB * b1;
                *(float2*)(out + (size_t)row1 * D + col) = o;
            }
        }
    }
}

// ---------------------------------------------------------------------------
extern "C" void kernel_launch(void* const* d_in, const int* in_sizes, int n_in,
                              void* d_out, int out_size) {
    const float* x   = (const float*)d_in[0];
    const int*   idx = (const int*)  d_in[1];
    const float* w   = (const float*)d_in[2];
    const float* Wg  = (const float*)d_in[3];
    const float* bg  = (const float*)d_in[4];
    const float* Wm  = (const float*)d_in[5];
    const float* bm  = (const float*)d_in[6];
    float* out = (float*)d_out;

    int N = in_sizes[1];
    int S = out_size / D;

    int quads = (N + 3) / 4;
    seg_starts_kernel<<<(quads + 255) / 256, 256>>>(idx, N, S);

    agg_kernel<<<AGG_BLOCKS, 256>>>(x, w, Wg, bg, S);

    gemm_kernel<<<(S + BM - 1) / BM, 256>>>(Wm, bm, out, S);
}